// round 3
// baseline (speedup 1.0000x reference)
#include <cuda_runtime.h>
#include <math.h>

#define NN   512
#define DD   128
#define M_TOTAL 2048   // 4*512

// Scratch (device globals: no allocation allowed in kernel_launch)
__device__ float g_Pb[M_TOTAL * DD];  // P + bias
__device__ float g_Q [M_TOTAL * DD];  // x @ W2

static __device__ __forceinline__ float4 f4max(float4 a, float4 b) {
    float4 r;
    r.x = fmaxf(a.x, b.x); r.y = fmaxf(a.y, b.y);
    r.z = fmaxf(a.z, b.z); r.w = fmaxf(a.w, b.w);
    return r;
}

// acc = max(acc, q + m) componentwise; m in {0, -1e38}: exact when m==0.
static __device__ __forceinline__ float4 f4maxadd(float4 acc, float4 q, float m) {
    acc.x = fmaxf(acc.x, q.x + m);
    acc.y = fmaxf(acc.y, q.y + m);
    acc.z = fmaxf(acc.z, q.z + m);
    acc.w = fmaxf(acc.w, q.w + m);
    return acc;
}

static __device__ __forceinline__ float4 f4fma(float s, float4 v, float4 acc) {
    acc.x = fmaf(s, v.x, acc.x);
    acc.y = fmaf(s, v.y, acc.y);
    acc.z = fmaf(s, v.z, acc.z);
    acc.w = fmaf(s, v.w, acc.w);
    return acc;
}

// ---------------------------------------------------------------------------
// Kernel 1: fused dual GEMM.
//   Pb[m,o] = sum_k x[m,k] * (W[k,o] - W[k+128,o]) + bias[o]
//   Q [m,o] = sum_k x[m,k] *  W[k+128,o]
// 256 blocks x 128 threads. Block = 8 rows; warp = 2 rows; lane = 4 cols.
// ---------------------------------------------------------------------------
__global__ __launch_bounds__(128)
void ec_gemm_kernel(const float* __restrict__ x,
                    const float* __restrict__ W,
                    const float* __restrict__ bias) {
    __shared__ float xs[8][DD];

    const int tid  = threadIdx.x;
    const int w    = tid >> 5;
    const int lane = tid & 31;
    const int rowBase = blockIdx.x * 8;

    // cooperative load of x tile: 8*128 = 1024 floats = 256 float4
    {
        const float4* x4 = (const float4*)(x + (size_t)rowBase * DD);
        float4*       s4 = (float4*)&xs[0][0];
        s4[tid]       = __ldg(&x4[tid]);
        s4[tid + 128] = __ldg(&x4[tid + 128]);
    }
    __syncthreads();

    const int r0 = w * 2;
    const float4 z = make_float4(0.f, 0.f, 0.f, 0.f);
    float4 aP0 = z, aP1 = z, aQ0 = z, aQ1 = z;

    const float4* __restrict__ W4 = (const float4*)W;

    for (int kc = 0; kc < DD; kc += 4) {
        const float4 xa = *(const float4*)&xs[r0][kc];
        const float4 xb = *(const float4*)&xs[r0 + 1][kc];

#define GSTEP(u, comp) {                                          \
        float4 w1 = __ldg(&W4[(kc + u) * 32 + lane]);             \
        float4 w2 = __ldg(&W4[(kc + u + DD) * 32 + lane]);        \
        float4 wd;                                                \
        wd.x = w1.x - w2.x; wd.y = w1.y - w2.y;                   \
        wd.z = w1.z - w2.z; wd.w = w1.w - w2.w;                   \
        aP0 = f4fma(xa.comp, wd, aP0);                            \
        aQ0 = f4fma(xa.comp, w2, aQ0);                            \
        aP1 = f4fma(xb.comp, wd, aP1);                            \
        aQ1 = f4fma(xb.comp, w2, aQ1); }

        GSTEP(0, x) GSTEP(1, y) GSTEP(2, z) GSTEP(3, w)
#undef GSTEP
    }

    const float4 b4 = __ldg(&((const float4*)bias)[lane]);
    const int m0 = rowBase + r0;

    float4* P4 = (float4*)g_Pb;
    float4* Q4 = (float4*)g_Q;

    float4 o0; o0.x = aP0.x + b4.x; o0.y = aP0.y + b4.y;
               o0.z = aP0.z + b4.z; o0.w = aP0.w + b4.w;
    float4 o1; o1.x = aP1.x + b4.x; o1.y = aP1.y + b4.y;
               o1.z = aP1.z + b4.z; o1.w = aP1.w + b4.w;

    P4[(size_t)m0 * 32 + lane]       = o0;
    P4[(size_t)(m0 + 1) * 32 + lane] = o1;
    Q4[(size_t)m0 * 32 + lane]       = aQ0;
    Q4[(size_t)(m0 + 1) * 32 + lane] = aQ1;
}

// ---------------------------------------------------------------------------
// Kernel 2: branchless masked neighbor max + epilogue.
//   out[b,i,o] = max(0, Pb[b,i,o] + max_j (Q[b,j,o] + m[i,j]))
// with m[i,j] = 0 if adj else -1e38 (exact masking).
// 512 blocks x 128 threads. Block = 4 i-rows; each warp scans 128 j's for all
// 4 rows (Q row loaded once, reused 4x); smem cross-warp max reduce.
// ---------------------------------------------------------------------------
__global__ __launch_bounds__(128)
void ec_maxred_kernel(const float* __restrict__ adj,
                      float* __restrict__ out) {
    __shared__ float  adjm[4][NN];
    __shared__ float4 part[4][4][32];   // [warp][row][colgroup]

    const int tid  = threadIdx.x;
    const int w    = tid >> 5;
    const int lane = tid & 31;
    const int i0   = blockIdx.x * 4;    // first global row (b*NN + i)
    const int b    = i0 >> 9;

    // load adj rows for 4 i's and transform to additive mask {0, -1e38}
    {
        const float4* a4 = (const float4*)(adj + (size_t)i0 * NN);
        float4*       s4 = (float4*)&adjm[0][0];
#pragma unroll
        for (int t = 0; t < 4; ++t) {
            float4 v = __ldg(&a4[tid + t * 128]);
            v.x = fmaf(v.x, 1e38f, -1e38f);
            v.y = fmaf(v.y, 1e38f, -1e38f);
            v.z = fmaf(v.z, 1e38f, -1e38f);
            v.w = fmaf(v.w, 1e38f, -1e38f);
            s4[tid + t * 128] = v;
        }
    }
    __syncthreads();

    const float4* __restrict__ Q4 = ((const float4*)g_Q) + (size_t)b * NN * 32;

    const float NEG = -3.0e38f;
    float4 acc0 = make_float4(NEG, NEG, NEG, NEG);
    float4 acc1 = acc0, acc2 = acc0, acc3 = acc0;

    const int jbase = w * 128;
    for (int jc = 0; jc < 128; jc += 4) {
        const int j0 = jbase + jc;
        const float4 m0 = *(const float4*)&adjm[0][j0];
        const float4 m1 = *(const float4*)&adjm[1][j0];
        const float4 m2 = *(const float4*)&adjm[2][j0];
        const float4 m3 = *(const float4*)&adjm[3][j0];

#define MSTEP(u, comp) {                                          \
        float4 q = __ldg(&Q4[(size_t)(j0 + u) * 32 + lane]);      \
        acc0 = f4maxadd(acc0, q, m0.comp);                        \
        acc1 = f4maxadd(acc1, q, m1.comp);                        \
        acc2 = f4maxadd(acc2, q, m2.comp);                        \
        acc3 = f4maxadd(acc3, q, m3.comp); }

        MSTEP(0, x) MSTEP(1, y) MSTEP(2, z) MSTEP(3, w)
#undef MSTEP
    }

    part[w][0][lane] = acc0;
    part[w][1][lane] = acc1;
    part[w][2][lane] = acc2;
    part[w][3][lane] = acc3;
    __syncthreads();

    // thread (w, lane) finalizes row (i0 + w), col group lane
    float4 v = part[0][w][lane];
    v = f4max(v, part[1][w][lane]);
    v = f4max(v, part[2][w][lane]);
    v = f4max(v, part[3][w][lane]);

    const float4 p = __ldg(&((const float4*)g_Pb)[(size_t)(i0 + w) * 32 + lane]);
    float4 r;
    r.x = fmaxf(0.f, p.x + v.x);
    r.y = fmaxf(0.f, p.y + v.y);
    r.z = fmaxf(0.f, p.z + v.z);
    r.w = fmaxf(0.f, p.w + v.w);
    ((float4*)out)[(size_t)(i0 + w) * 32 + lane] = r;
}

// ---------------------------------------------------------------------------
extern "C" void kernel_launch(void* const* d_in, const int* in_sizes, int n_in,
                              void* d_out, int out_size) {
    const float* x    = (const float*)d_in[0];   // (4,512,128)
    const float* adj  = (const float*)d_in[1];   // (4,512,512)
    const float* W    = (const float*)d_in[2];   // (256,128)
    const float* bias = (const float*)d_in[3];   // (128,)
    float*       out  = (float*)d_out;           // (4,512,128)

    ec_gemm_kernel<<<M_TOTAL / 8, 128>>>(x, W, bias);
    ec_maxred_kernel<<<M_TOTAL / 4, 128>>>(adj, out);
}